// round 7
// baseline (speedup 1.0000x reference)
#include <cuda_runtime.h>

#define NNODES 100000
#define NEDGES 1000000
#define NGRAPHS 1000
#define EMBED 64
#define OUTDIM 128
#define NCONV 3
#define BN_EPS 1e-5f

#define SCAN_BLOCKS ((NNODES + 255) / 256)   // 391
#define SB_BLOCKS 391                         // stats+bn fused grid (resident-safe)

typedef unsigned long long u64;

// ---------------- scratch (no allocs allowed) ----------------
// stats MUST be 16B-aligned (float4 loads) -> placed first.
struct alignas(16) ZBuf {     // zeroed via one cudaMemsetAsync each call
    float stats[NCONV * 2 * EMBED];   // offset 0, 1536 B (mult of 16)
    int   deg[NNODES];
    int   cnt;                 // scan arrival counter
    int   done;                // scan completion flag
    int   bn_cnt[NCONV];       // per-layer stats arrival counters
    int   bn_done[NCONV];      // per-layer stats completion flags
};
__device__ ZBuf d_Z;

__device__ float d_h[NNODES * EMBED];      // node features
__device__ float d_t[NNODES * EMBED];      // agg + h (GEMM input)
__device__ float d_y[NNODES * EMBED];      // GEMM output (pre-BN)
__device__ int   d_rowptr[NNODES + 1];
__device__ int   d_cursor[NNODES];
__device__ int   d_aggr[512];
__device__ int   d_off[512];
__device__ unsigned d_edge[NEDGES];        // packed: (src << 8) | efeat
__device__ float d_gn[NGRAPHS * EMBED];

// ---------------- f32x2 helpers ----------------
__device__ __forceinline__ u64 ffma2(u64 a, u64 b, u64 c) {
    u64 d;
    asm("fma.rn.f32x2 %0, %1, %2, %3;" : "=l"(d) : "l"(a), "l"(b), "l"(c));
    return d;
}
__device__ __forceinline__ u64 pack2(float x) {
    u64 d;
    asm("mov.b64 %0, {%1, %1};" : "=l"(d) : "f"(x));
    return d;
}

// ---------------- setup kernels ----------------
__global__ void k_embed_count(const int* __restrict__ nfeat,
                              const float4* __restrict__ atom_embed,
                              const int* __restrict__ dst) {
    int i = blockIdx.x * 256 + threadIdx.x;
    if (i < NNODES * 16) {
        int n = i >> 4, c4 = i & 15;
        ((float4*)d_h)[i] = atom_embed[nfeat[n] * 16 + c4];
    }
    if (i < NEDGES) atomicAdd(&d_Z.deg[dst[i]], 1);
}

// single-kernel exclusive scan: block-local scan, last-arriving block computes
// the 391 block offsets, everyone else spins. 391 blocks all resident -> safe.
__global__ void k_scan() {
    __shared__ int s[256];
    __shared__ int s2[256];
    __shared__ int sdone;
    int t = threadIdx.x, bid = blockIdx.x;
    int i = bid * 256 + t;
    int v = (i < NNODES) ? d_Z.deg[i] : 0;
    s[t] = v;
    __syncthreads();
    #pragma unroll
    for (int off = 1; off < 256; off <<= 1) {
        int u = (t >= off) ? s[t - off] : 0;
        __syncthreads();
        s[t] += u;
        __syncthreads();
    }
    int lexcl = s[t] - v;
    int agg = s[255];
    if (t == 0) {
        d_aggr[bid] = agg;
        __threadfence();
        int old = atomicAdd(&d_Z.cnt, 1);
        sdone = (old == SCAN_BLOCKS - 1);
    }
    __syncthreads();
    if (sdone) {
        int a0 = (2 * t < SCAN_BLOCKS) ? d_aggr[2 * t] : 0;
        int a1 = (2 * t + 1 < SCAN_BLOCKS) ? d_aggr[2 * t + 1] : 0;
        s2[t] = a0 + a1;
        __syncthreads();
        #pragma unroll
        for (int off = 1; off < 256; off <<= 1) {
            int u = (t >= off) ? s2[t - off] : 0;
            __syncthreads();
            s2[t] += u;
            __syncthreads();
        }
        int ex = s2[t] - (a0 + a1);
        d_off[2 * t] = ex;
        d_off[2 * t + 1] = ex + a0;
        if (t == 255) d_rowptr[NNODES] = s2[255];
        __threadfence();
        if (t == 0) atomicExch(&d_Z.done, 1);
    }
    if (t == 0) {
        while (atomicAdd(&d_Z.done, 0) == 0) __nanosleep(40);
    }
    __syncthreads();
    int boff = __ldcg(&d_off[bid]);
    if (i < NNODES) {
        int r = lexcl + boff;
        d_rowptr[i] = r;
        d_cursor[i] = r;
    }
}

__global__ void k_fill(const int* __restrict__ src,
                       const int* __restrict__ efeat,
                       const int* __restrict__ dst) {
    int e = blockIdx.x * blockDim.x + threadIdx.x;
    if (e >= NEDGES) return;
    int p = atomicAdd(&d_cursor[dst[e]], 1);
    d_edge[p] = ((unsigned)src[e] << 8) | (unsigned)efeat[e];
}

// ---------------- per-layer kernels ----------------
// warp per node; within the warp, lanes 0-15 process even edges, lanes 16-31
// odd edges (same node, so trip counts differ by <=1). Each lane covers 4
// channels: one warp LDG.128 gathers the h-rows for TWO edges.
// t[n] = mean_e relu(bond[ef] + h[src]) + h[n]
__global__ void __launch_bounds__(256) k_msg(const float* __restrict__ bond) {
    __shared__ __align__(16) float4 bsh[5 * 16];
    int tid = threadIdx.x;
    if (tid < 80) bsh[tid] = ((const float4*)bond)[tid];
    __syncthreads();
    int warp = tid >> 5, lane = tid & 31;
    int half = lane >> 4, hl = lane & 15;
    int node = blockIdx.x * 8 + warp;
    if (node >= NNODES) return;
    int rs = d_rowptr[node], re = d_rowptr[node + 1];
    int cnt = re - rs;
    const char* hbase = (const char*)d_h + hl * 16;
    const char* bbase = (const char*)bsh + hl * 16;
    float4 s0 = make_float4(0.f, 0.f, 0.f, 0.f), s1 = s0;
    int i = rs + half;                 // this half's first edge
    for (; i + 2 < re; i += 4) {       // 2 edges per half per iter
        unsigned p0 = d_edge[i], p1 = d_edge[i + 2];
        float4 h0 = *(const float4*)(hbase + (p0 & 0xFFFFFF00u));
        float4 h1 = *(const float4*)(hbase + (p1 & 0xFFFFFF00u));
        float4 b0 = *(const float4*)(bbase + ((p0 & 255u) << 8));
        float4 b1 = *(const float4*)(bbase + ((p1 & 255u) << 8));
        s0.x += fmaxf(b0.x + h0.x, 0.f); s0.y += fmaxf(b0.y + h0.y, 0.f);
        s0.z += fmaxf(b0.z + h0.z, 0.f); s0.w += fmaxf(b0.w + h0.w, 0.f);
        s1.x += fmaxf(b1.x + h1.x, 0.f); s1.y += fmaxf(b1.y + h1.y, 0.f);
        s1.z += fmaxf(b1.z + h1.z, 0.f); s1.w += fmaxf(b1.w + h1.w, 0.f);
    }
    if (i < re) {                       // at most one leftover edge per half
        unsigned p0 = d_edge[i];
        float4 h0 = *(const float4*)(hbase + (p0 & 0xFFFFFF00u));
        float4 b0 = *(const float4*)(bbase + ((p0 & 255u) << 8));
        s0.x += fmaxf(b0.x + h0.x, 0.f); s0.y += fmaxf(b0.y + h0.y, 0.f);
        s0.z += fmaxf(b0.z + h0.z, 0.f); s0.w += fmaxf(b0.w + h0.w, 0.f);
    }
    s0.x += s1.x; s0.y += s1.y; s0.z += s1.z; s0.w += s1.w;
    s0.x += __shfl_xor_sync(0xffffffffu, s0.x, 16);
    s0.y += __shfl_xor_sync(0xffffffffu, s0.y, 16);
    s0.z += __shfl_xor_sync(0xffffffffu, s0.z, 16);
    s0.w += __shfl_xor_sync(0xffffffffu, s0.w, 16);
    if (half == 0) {
        float inv = 1.f / (float)(cnt > 0 ? cnt : 1);
        float4 hn = ((const float4*)(d_h + (size_t)node * EMBED))[hl];
        float4 o;
        o.x = s0.x * inv + hn.x;
        o.y = s0.y * inv + hn.y;
        o.z = s0.z * inv + hn.z;
        o.w = s0.w * inv + hn.w;
        ((float4*)(d_t + (size_t)node * EMBED))[hl] = o;
    }
}

// thread per node: y = t @ W + b, packed f32x2 FMA, all 64 outputs live.
__global__ void __launch_bounds__(256) k_gemm(const float* __restrict__ W,
                                              const float* __restrict__ b) {
    __shared__ ulonglong2 Ws[EMBED * 16];
    int tid = threadIdx.x;
    for (int i = tid; i < EMBED * 16; i += 256) Ws[i] = ((const ulonglong2*)W)[i];
    __syncthreads();
    int node = blockIdx.x * 256 + tid;
    if (node >= NNODES) return;
    u64 acc[32];
    const u64* bp = (const u64*)b;
    #pragma unroll
    for (int i = 0; i < 32; i++) acc[i] = bp[i];
    const float4* tp = (const float4*)(d_t + (size_t)node * EMBED);
    #pragma unroll 1
    for (int k4 = 0; k4 < 16; k4++) {
        float4 tv = tp[k4];
        #pragma unroll
        for (int j = 0; j < 4; j++) {
            float tk = (j == 0) ? tv.x : (j == 1) ? tv.y : (j == 2) ? tv.z : tv.w;
            u64 tkk = pack2(tk);
            int k = k4 * 4 + j;
            #pragma unroll
            for (int c8 = 0; c8 < 16; c8++) {
                ulonglong2 w = Ws[k * 16 + c8];
                acc[2 * c8]     = ffma2(tkk, w.x, acc[2 * c8]);
                acc[2 * c8 + 1] = ffma2(tkk, w.y, acc[2 * c8 + 1]);
            }
        }
    }
    ulonglong2* yp = (ulonglong2*)(d_y + (size_t)node * EMBED);
    #pragma unroll
    for (int i = 0; i < 16; i++)
        yp[i] = make_ulonglong2(acc[2 * i], acc[2 * i + 1]);
}

// fused batch-norm: phase 1 per-channel sum/sumsq partials + global atomics,
// spin until all blocks contributed, phase 2 normalize+relu+residual.
// SB_BLOCKS=391 blocks all resident -> spin is safe.
__global__ void __launch_bounds__(256) k_statsbn(int layer,
                                                 const float* __restrict__ gamma,
                                                 const float* __restrict__ beta,
                                                 int do_relu) {
    __shared__ float4 ssum[256], ssq[256];
    int tid = threadIdx.x;
    int c4 = tid & 15, grp = tid >> 4;   // 16 row-groups x 16 float4-channels
    float4 sum = make_float4(0.f, 0.f, 0.f, 0.f), sq = sum;
    for (int row = blockIdx.x * 16 + grp; row < NNODES; row += SB_BLOCKS * 16) {
        float4 v = ((const float4*)d_y)[row * 16 + c4];
        sum.x += v.x; sum.y += v.y; sum.z += v.z; sum.w += v.w;
        sq.x += v.x * v.x; sq.y += v.y * v.y; sq.z += v.z * v.z; sq.w += v.w * v.w;
    }
    ssum[tid] = sum; ssq[tid] = sq;
    __syncthreads();
    if (grp == 0) {
        #pragma unroll
        for (int g = 1; g < 16; g++) {
            float4 a = ssum[g * 16 + c4], q = ssq[g * 16 + c4];
            sum.x += a.x; sum.y += a.y; sum.z += a.z; sum.w += a.w;
            sq.x += q.x; sq.y += q.y; sq.z += q.z; sq.w += q.w;
        }
        float* st = d_Z.stats + layer * 128;
        atomicAdd(&st[c4 * 4 + 0], sum.x);
        atomicAdd(&st[c4 * 4 + 1], sum.y);
        atomicAdd(&st[c4 * 4 + 2], sum.z);
        atomicAdd(&st[c4 * 4 + 3], sum.w);
        atomicAdd(&st[64 + c4 * 4 + 0], sq.x);
        atomicAdd(&st[64 + c4 * 4 + 1], sq.y);
        atomicAdd(&st[64 + c4 * 4 + 2], sq.z);
        atomicAdd(&st[64 + c4 * 4 + 3], sq.w);
    }
    __syncthreads();
    if (tid == 0) {
        __threadfence();
        int old = atomicAdd(&d_Z.bn_cnt[layer], 1);
        if (old == SB_BLOCKS - 1) atomicExch(&d_Z.bn_done[layer], 1);
        while (atomicAdd(&d_Z.bn_done[layer], 0) == 0) __nanosleep(40);
    }
    __syncthreads();
    // phase 2: normalize
    const float invN = 1.f / (float)NNODES;
    const float* st = d_Z.stats + layer * 128;
    float4 s1, s2;
    s1.x = __ldcg(&st[c4 * 4 + 0]); s1.y = __ldcg(&st[c4 * 4 + 1]);
    s1.z = __ldcg(&st[c4 * 4 + 2]); s1.w = __ldcg(&st[c4 * 4 + 3]);
    s2.x = __ldcg(&st[64 + c4 * 4 + 0]); s2.y = __ldcg(&st[64 + c4 * 4 + 1]);
    s2.z = __ldcg(&st[64 + c4 * 4 + 2]); s2.w = __ldcg(&st[64 + c4 * 4 + 3]);
    float4 g  = ((const float4*)gamma)[c4];
    float4 be = ((const float4*)beta)[c4];
    float4 mu, rs;
    #define PREP(X) { \
        mu.X = s1.X * invN; \
        float var = s2.X * invN - mu.X * mu.X; \
        rs.X = rsqrtf(fmaxf(var, 0.f) + BN_EPS) * g.X; }
    PREP(x) PREP(y) PREP(z) PREP(w)
    #undef PREP
    for (int row = blockIdx.x * 16 + grp; row < NNODES; row += SB_BLOCKS * 16) {
        int idx = row * 16 + c4;
        float4 y = ((const float4*)d_y)[idx];
        float4 h = ((const float4*)d_h)[idx];
        float v;
        #define BN1(X) \
            v = (y.X - mu.X) * rs.X + be.X; \
            if (do_relu) v = fmaxf(v, 0.f); \
            h.X += v;
        BN1(x) BN1(y) BN1(z) BN1(w)
        #undef BN1
        ((float4*)d_h)[idx] = h;
    }
}

// ---------------- tail kernels ----------------
__global__ void k_pool(const int* __restrict__ gids) {
    __shared__ float red[256];
    __shared__ int range[2];
    int g = blockIdx.x, tid = threadIdx.x;
    int c = tid & 63, grp = tid >> 6;
    if (tid < 2) {
        int target = g + tid;
        int lo = 0, hi = NNODES;
        while (lo < hi) { int m = (lo + hi) >> 1; if (gids[m] < target) lo = m + 1; else hi = m; }
        range[tid] = lo;
    }
    __syncthreads();
    int start = range[0], end = range[1];
    float acc = 0.f;
    for (int n = start + grp; n < end; n += 4)
        acc += d_h[(size_t)n * EMBED + c];
    red[tid] = acc;
    __syncthreads();
    if (grp == 0) {
        float s = red[c] + red[64 + c] + red[128 + c] + red[192 + c];
        int cntg = end - start;
        d_gn[g * EMBED + c] = s / (float)(cntg > 0 ? cntg : 1);
    }
}

__global__ void k_pred(const float* __restrict__ W, const float* __restrict__ b,
                       float* __restrict__ out) {
    __shared__ float gs[EMBED];
    int g = blockIdx.x, o = threadIdx.x;
    if (o < EMBED) gs[o] = d_gn[g * EMBED + o];
    __syncthreads();
    float acc = b[o];
    #pragma unroll
    for (int k = 0; k < EMBED; k++) acc += gs[k] * W[k * OUTDIM + o];
    out[g * OUTDIM + o] = acc;
}

// ---------------- launch ----------------
extern "C" void kernel_launch(void* const* d_in, const int* in_sizes, int n_in,
                              void* d_out, int out_size) {
    const int*   nfeat      = (const int*)d_in[0];
    const int*   efeat      = (const int*)d_in[1];
    const int*   src        = (const int*)d_in[2];
    const int*   dst        = (const int*)d_in[3];
    const int*   gids       = (const int*)d_in[4];
    const float* atom_embed = (const float*)d_in[5];
    const float* bond_embed = (const float*)d_in[6];
    const float* conv_W     = (const float*)d_in[7];
    const float* conv_b     = (const float*)d_in[8];
    const float* bn_gamma   = (const float*)d_in[9];
    const float* bn_beta    = (const float*)d_in[10];
    const float* pred_W     = (const float*)d_in[11];
    const float* pred_b     = (const float*)d_in[12];
    float* out = (float*)d_out;

    void* zp = nullptr;
    cudaGetSymbolAddress(&zp, d_Z);
    cudaMemsetAsync(zp, 0, sizeof(ZBuf), 0);

    k_embed_count<<<(NNODES * 16 + 255) / 256, 256>>>(nfeat, (const float4*)atom_embed, dst);
    k_scan<<<SCAN_BLOCKS, 256>>>();
    k_fill<<<(NEDGES + 255) / 256, 256>>>(src, efeat, dst);

    for (int i = 0; i < NCONV; i++) {
        k_msg<<<(NNODES + 7) / 8, 256>>>(bond_embed + i * 5 * EMBED);
        k_gemm<<<(NNODES + 255) / 256, 256>>>(conv_W + i * EMBED * EMBED,
                                              conv_b + i * EMBED);
        k_statsbn<<<SB_BLOCKS, 256>>>(i, bn_gamma + i * EMBED,
                                      bn_beta + i * EMBED,
                                      (i < NCONV - 1) ? 1 : 0);
    }

    k_pool<<<NGRAPHS, 256>>>(gids);
    k_pred<<<NGRAPHS, OUTDIM>>>(pred_W, pred_b, out);
}